// round 1
// baseline (speedup 1.0000x reference)
#include <cuda_runtime.h>
#include <cstdint>

// Problem shape (fixed per reference): B=4, S=4096, E=1024, H=16, D=64
#define M_TOT 16384   // B*S tokens
#define N_TOT 1024    // E
#define K_TOT 1024    // E

static constexpr int BM = 128;
static constexpr int BN = 128;
static constexpr int BK = 16;
static constexpr int TM = 8;
static constexpr int TN = 8;
static constexpr int GEMM_THREADS = 256;

// Scratch for Q, K, V projections: 3 * 16384 * 1024 fp32 = 192 MB (static device mem, allowed)
__device__ float g_qkv[3][(size_t)M_TOT * N_TOT];

// ---- packed f32x2 helpers (Blackwell: FFMA2 doubles fp32 throughput vs 3-reg FFMA) ----
__device__ __forceinline__ unsigned long long pack2_same(float x) {
    unsigned long long r;
    asm("mov.b64 %0, {%1, %1};" : "=l"(r) : "f"(x));
    return r;
}
__device__ __forceinline__ void ffma2(unsigned long long& d, unsigned long long a, unsigned long long b) {
    asm("fma.rn.f32x2 %0, %1, %2, %0;" : "+l"(d) : "l"(a), "l"(b));
}
__device__ __forceinline__ void unpack2(unsigned long long p, float& lo, float& hi) {
    asm("mov.b64 {%0, %1}, %2;" : "=f"(lo), "=f"(hi) : "l"(p));
}

// ============================================================================
// Fused QKV projection GEMM: out[z] = x @ W[z] + b[z],  z in {Q,K,V}
// C[M,N] = A[M,K] @ B[K,N], all row-major. 128x128 tile, BK=16, 8x8 microtile.
// Double-buffered SMEM, packed-f32x2 inner product.
// ============================================================================
__global__ __launch_bounds__(GEMM_THREADS, 2)
void qkv_gemm(const float* __restrict__ x,
              const float* __restrict__ Wq, const float* __restrict__ bq,
              const float* __restrict__ Wk, const float* __restrict__ bk,
              const float* __restrict__ Wv, const float* __restrict__ bv)
{
    const int z = blockIdx.z;
    const float* __restrict__ W    = (z == 0) ? Wq : (z == 1) ? Wk : Wv;
    const float* __restrict__ bias = (z == 0) ? bq : (z == 1) ? bk : bv;
    float* __restrict__ out = g_qkv[z];

    // As transposed [k][m] with +4 pad to reduce store bank conflicts
    __shared__ float As[2][BK][BM + 4];
    __shared__ float Bs[2][BK][BN];

    const int tid = threadIdx.x;
    const int ty = tid >> 4;        // 0..15
    const int tx = tid & 15;        // 0..15
    const int m0 = blockIdx.y * BM;
    const int n0 = blockIdx.x * BN;

    // A loader: 128 rows x 16 cols = 512 float4; 2 per thread
    const int aM = tid >> 2;            // 0..63 (and +64)
    const int aK = (tid & 3) * 4;       // 0,4,8,12
    // B loader: 16 rows x 128 cols = 512 float4; 2 per thread
    const int bKr = tid >> 5;           // 0..7 (and +8)
    const int bNc = (tid & 31) * 4;

    const float* Aptr = x + (size_t)m0 * K_TOT;
    const float* Bptr = W + n0;

    unsigned long long acc[TM][TN / 2];
    #pragma unroll
    for (int i = 0; i < TM; i++)
        #pragma unroll
        for (int j = 0; j < TN / 2; j++) acc[i][j] = 0ull;

    float4 aReg0, aReg1, bReg0, bReg1;

    // prefetch tile 0
    aReg0 = *(const float4*)(Aptr + (size_t)aM        * K_TOT + aK);
    aReg1 = *(const float4*)(Aptr + (size_t)(aM + 64) * K_TOT + aK);
    bReg0 = *(const float4*)(Bptr + (size_t)bKr       * N_TOT + bNc);
    bReg1 = *(const float4*)(Bptr + (size_t)(bKr + 8) * N_TOT + bNc);

    // store tile 0 into buffer 0
    As[0][aK + 0][aM] = aReg0.x;  As[0][aK + 1][aM] = aReg0.y;
    As[0][aK + 2][aM] = aReg0.z;  As[0][aK + 3][aM] = aReg0.w;
    As[0][aK + 0][aM + 64] = aReg1.x;  As[0][aK + 1][aM + 64] = aReg1.y;
    As[0][aK + 2][aM + 64] = aReg1.z;  As[0][aK + 3][aM + 64] = aReg1.w;
    *(float4*)&Bs[0][bKr][bNc]     = bReg0;
    *(float4*)&Bs[0][bKr + 8][bNc] = bReg1;
    __syncthreads();

    const int NT = K_TOT / BK;  // 64
    for (int t = 0; t < NT; ++t) {
        const int buf = t & 1;
        if (t + 1 < NT) {
            const int kk = (t + 1) * BK;
            aReg0 = *(const float4*)(Aptr + (size_t)aM        * K_TOT + kk + aK);
            aReg1 = *(const float4*)(Aptr + (size_t)(aM + 64) * K_TOT + kk + aK);
            bReg0 = *(const float4*)(Bptr + (size_t)(kk + bKr)     * N_TOT + bNc);
            bReg1 = *(const float4*)(Bptr + (size_t)(kk + bKr + 8) * N_TOT + bNc);
        }

        #pragma unroll
        for (int k = 0; k < BK; k++) {
            float4 a0 = *(const float4*)&As[buf][k][ty * TM];
            float4 a1 = *(const float4*)&As[buf][k][ty * TM + 4];
            unsigned long long b2[4];
            b2[0] = *(const unsigned long long*)&Bs[buf][k][tx * TN + 0];
            b2[1] = *(const unsigned long long*)&Bs[buf][k][tx * TN + 2];
            b2[2] = *(const unsigned long long*)&Bs[buf][k][tx * TN + 4];
            b2[3] = *(const unsigned long long*)&Bs[buf][k][tx * TN + 6];
            float av[8] = {a0.x, a0.y, a0.z, a0.w, a1.x, a1.y, a1.z, a1.w};
            #pragma unroll
            for (int i = 0; i < 8; i++) {
                unsigned long long ap = pack2_same(av[i]);
                #pragma unroll
                for (int j = 0; j < 4; j++) ffma2(acc[i][j], ap, b2[j]);
            }
        }

        if (t + 1 < NT) {
            const int nbuf = buf ^ 1;
            As[nbuf][aK + 0][aM] = aReg0.x;  As[nbuf][aK + 1][aM] = aReg0.y;
            As[nbuf][aK + 2][aM] = aReg0.z;  As[nbuf][aK + 3][aM] = aReg0.w;
            As[nbuf][aK + 0][aM + 64] = aReg1.x;  As[nbuf][aK + 1][aM + 64] = aReg1.y;
            As[nbuf][aK + 2][aM + 64] = aReg1.z;  As[nbuf][aK + 3][aM + 64] = aReg1.w;
            *(float4*)&Bs[nbuf][bKr][bNc]     = bReg0;
            *(float4*)&Bs[nbuf][bKr + 8][bNc] = bReg1;
            __syncthreads();
        }
    }

    // epilogue: unpack, add bias, vectorized store
    const int cBase = n0 + tx * TN;
    float bv4[8];
    #pragma unroll
    for (int j = 0; j < 8; j++) bv4[j] = bias[cBase + j];

    float* outp = out + (size_t)(m0 + ty * TM) * N_TOT + cBase;
    #pragma unroll
    for (int i = 0; i < TM; i++) {
        float c[8];
        #pragma unroll
        for (int j = 0; j < 4; j++) unpack2(acc[i][j], c[2 * j], c[2 * j + 1]);
        float4 r0 = {c[0] + bv4[0], c[1] + bv4[1], c[2] + bv4[2], c[3] + bv4[3]};
        float4 r1 = {c[4] + bv4[4], c[5] + bv4[5], c[6] + bv4[6], c[7] + bv4[7]};
        *(float4*)(outp + (size_t)i * N_TOT)     = r0;
        *(float4*)(outp + (size_t)i * N_TOT + 4) = r1;
    }
}

// ============================================================================
// Per-token attention: for each token, q,k,v are [H=16][D=64].
// att = q @ k^T (16x16, no scale/softmax), out = att @ v.
// One block per token, 256 threads. Padded SMEM strides to avoid bank conflicts.
// ============================================================================
__global__ __launch_bounds__(256)
void attn_kernel(float* __restrict__ out)
{
    const int tok = blockIdx.x;
    __shared__ float qs[16 * 65];   // [h][d], stride 65 -> conflict-free k-dot
    __shared__ float ks[16 * 65];
    __shared__ float vs[16 * 68];   // stride 68 keeps float4 alignment
    __shared__ float att[16 * 17];

    const int tid = threadIdx.x;
    const float* __restrict__ q = g_qkv[0] + (size_t)tok * 1024;
    const float* __restrict__ k = g_qkv[1] + (size_t)tok * 1024;
    const float* __restrict__ v = g_qkv[2] + (size_t)tok * 1024;

    // load q,k,v: 1024 floats each; one float4 per thread per array
    {
        const int e = tid * 4;
        const int h = e >> 6;
        const int d = e & 63;
        float4 qv = *(const float4*)(q + e);
        qs[h * 65 + d + 0] = qv.x; qs[h * 65 + d + 1] = qv.y;
        qs[h * 65 + d + 2] = qv.z; qs[h * 65 + d + 3] = qv.w;
        float4 kv = *(const float4*)(k + e);
        ks[h * 65 + d + 0] = kv.x; ks[h * 65 + d + 1] = kv.y;
        ks[h * 65 + d + 2] = kv.z; ks[h * 65 + d + 3] = kv.w;
        float4 vv = *(const float4*)(v + e);
        *(float4*)&vs[h * 68 + d] = vv;
    }
    __syncthreads();

    // att[h][t] = sum_d q[h][d] * k[t][d]  (256 threads = 256 (h,t) pairs)
    {
        const int h = tid >> 4;
        const int t = tid & 15;
        float s = 0.f;
        #pragma unroll
        for (int d = 0; d < 64; d++) s += qs[h * 65 + d] * ks[t * 65 + d];
        att[h * 17 + t] = s;
    }
    __syncthreads();

    // out[h][d] = sum_t att[h][t] * v[t][d]; each thread does 4 d's
    {
        const int h = tid >> 4;
        const int dv = (tid & 15) * 4;
        float4 o = {0.f, 0.f, 0.f, 0.f};
        #pragma unroll
        for (int t = 0; t < 16; t++) {
            const float a = att[h * 17 + t];
            float4 vv = *(const float4*)&vs[t * 68 + dv];
            o.x += a * vv.x; o.y += a * vv.y; o.z += a * vv.z; o.w += a * vv.w;
        }
        *(float4*)(out + (size_t)tok * 1024 + h * 64 + dv) = o;
    }
}

extern "C" void kernel_launch(void* const* d_in, const int* in_sizes, int n_in,
                              void* d_out, int out_size)
{
    const float* x  = (const float*)d_in[0];
    const float* Wq = (const float*)d_in[1];
    const float* bq = (const float*)d_in[2];
    const float* Wk = (const float*)d_in[3];
    const float* bk = (const float*)d_in[4];
    const float* Wv = (const float*)d_in[5];
    const float* bv = (const float*)d_in[6];
    float* out = (float*)d_out;

    dim3 ggrid(N_TOT / BN, M_TOT / BM, 3);   // 8 x 128 x 3
    qkv_gemm<<<ggrid, GEMM_THREADS>>>(x, Wq, bq, Wk, bk, Wv, bv);
    attn_kernel<<<M_TOT, 256>>>(out);
}

// round 3
// speedup vs baseline: 2.5614x; 2.5614x over previous
#include <cuda_runtime.h>
#include <cuda_bf16.h>
#include <cstdint>

// Problem shape: B=4, S=4096, E=1024, H=16, D=64
#define M_TOT 16384
#define N_TOT 1024
#define K_TOT 1024

// ---------------- static device scratch ----------------
__device__ float g_qkv[3][(size_t)M_TOT * N_TOT];                 // 192 MB
__device__ __nv_bfloat16 g_xh[(size_t)M_TOT * K_TOT];             // 32 MB
__device__ __nv_bfloat16 g_xl[(size_t)M_TOT * K_TOT];             // 32 MB
__device__ __nv_bfloat16 g_wh[3][(size_t)K_TOT * N_TOT];          // transposed [n][k]
__device__ __nv_bfloat16 g_wl[3][(size_t)K_TOT * N_TOT];

// ---------------- PTX helpers (sm_80-compatible only) ----------------
__device__ __forceinline__ uint32_t sptr(const void* p) {
    return (uint32_t)__cvta_generic_to_shared(p);
}
__device__ __forceinline__ void cpa16(uint32_t s, const void* g) {
    asm volatile("cp.async.cg.shared.global [%0], [%1], 16;" :: "r"(s), "l"(g) : "memory");
}
__device__ __forceinline__ void cp_commit() { asm volatile("cp.async.commit_group;" ::: "memory"); }
template <int N> __device__ __forceinline__ void cp_wait() {
    asm volatile("cp.async.wait_group %0;" :: "n"(N) : "memory");
}
__device__ __forceinline__ void ldm_x4(uint32_t& r0, uint32_t& r1, uint32_t& r2, uint32_t& r3,
                                       uint32_t addr) {
    asm volatile("ldmatrix.sync.aligned.m8n8.x4.shared.b16 {%0,%1,%2,%3}, [%4];"
                 : "=r"(r0), "=r"(r1), "=r"(r2), "=r"(r3) : "r"(addr));
}
__device__ __forceinline__ void mma_bf16(float* c, const uint32_t* a, const uint32_t* b) {
    asm volatile(
        "mma.sync.aligned.m16n8k16.row.col.f32.bf16.bf16.f32 "
        "{%0,%1,%2,%3}, {%4,%5,%6,%7}, {%8,%9}, {%0,%1,%2,%3};"
        : "+f"(c[0]), "+f"(c[1]), "+f"(c[2]), "+f"(c[3])
        : "r"(a[0]), "r"(a[1]), "r"(a[2]), "r"(a[3]), "r"(b[0]), "r"(b[1]));
}

#define SWZ(o) ((o) ^ (((o) >> 3) & 0x70))

// ---------------- split kernels ----------------
__global__ __launch_bounds__(256)
void split_x_kernel(const float* __restrict__ x) {
    size_t i = ((size_t)blockIdx.x * 256 + threadIdx.x) * 4;
    float4 v = *(const float4*)(x + i);
    float f[4] = {v.x, v.y, v.z, v.w};
    union { __nv_bfloat16 b[4]; uint2 u; } uh, ul;
    #pragma unroll
    for (int j = 0; j < 4; j++) {
        __nv_bfloat16 hb = __float2bfloat16_rn(f[j]);
        float r = f[j] - __bfloat162float(hb);
        uh.b[j] = hb;
        ul.b[j] = __float2bfloat16_rn(r);
    }
    *(uint2*)(g_xh + i) = uh.u;
    *(uint2*)(g_xl + i) = ul.u;
}

// transpose + split W[k][n] -> Wh^T[n][k], Wl^T[n][k]
__global__ __launch_bounds__(1024)
void split_w_kernel(const float* __restrict__ Wq, const float* __restrict__ Wk,
                    const float* __restrict__ Wv) {
    const int z = blockIdx.z;
    const float* __restrict__ W = (z == 0) ? Wq : (z == 1) ? Wk : Wv;
    __shared__ float tile[32][33];
    const int k0 = blockIdx.y * 32, n0 = blockIdx.x * 32;
    const int tx = threadIdx.x, ty = threadIdx.y;
    tile[ty][tx] = W[(size_t)(k0 + ty) * N_TOT + n0 + tx];
    __syncthreads();
    float f = tile[tx][ty];  // = W[k0+tx][n0+ty]
    __nv_bfloat16 hb = __float2bfloat16_rn(f);
    float r = f - __bfloat162float(hb);
    size_t o = (size_t)(n0 + ty) * K_TOT + k0 + tx;
    g_wh[z][o] = hb;
    g_wl[z][o] = __float2bfloat16_rn(r);
}

// ---------------- mma.sync bf16 GEMM with split-K'=3072 ----------------
// CTA 128x128, BK=64 (128B rows, SW128 swizzle), 3-stage cp.async pipeline.
// 8 warps: warp_m = wid&1 (64 rows), warp_n = wid>>1 (32 cols). 48 k-tiles.
static constexpr int STAGE_BYTES = 32768;         // A 16K + B 16K
static constexpr int SMEM_DYN = 3 * STAGE_BYTES;  // 96 KB
static constexpr int NKT = 48;                    // 3072 / 64

__device__ __forceinline__ void load_stage(uint32_t sbase, int slot, int kt,
                                           int m0, int n0, int tid,
                                           const __nv_bfloat16* wh,
                                           const __nv_bfloat16* wl)
{
    const int reg = kt >> 4;
    const int kb = (kt & 15) * 64;
    const __nv_bfloat16* __restrict__ Asrc = (reg < 2) ? g_xh : g_xl;
    const __nv_bfloat16* __restrict__ Bsrc = (reg == 1) ? wl : wh;
    const uint32_t abase = sbase + (uint32_t)slot * STAGE_BYTES;
    const uint32_t bbase = abase + 16384;
    #pragma unroll
    for (int i = 0; i < 4; i++) {
        int idx = tid + i * 256;
        int row = idx >> 3, c = idx & 7;
        uint32_t so = SWZ((uint32_t)(row * 128 + c * 16));
        cpa16(abase + so, Asrc + (((size_t)(m0 + row)) << 10) + kb + c * 8);
        cpa16(bbase + so, Bsrc + (((size_t)(n0 + row)) << 10) + kb + c * 8);
    }
}

__global__ __launch_bounds__(256, 2)
void qkv_gemm_mma(const float* __restrict__ bq, const float* __restrict__ bk,
                  const float* __restrict__ bv)
{
    extern __shared__ __align__(16) char dsm[];
    __shared__ float bias_sh[128];

    const int tid = threadIdx.x;
    const int lane = tid & 31;
    const int wid = tid >> 5;
    const int warp_m = wid & 1;        // 0..1 -> 64-row halves
    const int warp_n = wid >> 1;       // 0..3 -> 32-col quarters
    const int z = blockIdx.z;
    const int n0 = blockIdx.x * 128;
    const int m0 = blockIdx.y * 128;

    const __nv_bfloat16* __restrict__ wh = g_wh[z];
    const __nv_bfloat16* __restrict__ wl = g_wl[z];
    const float* __restrict__ bias = (z == 0) ? bq : (z == 1) ? bk : bv;
    float* __restrict__ out = g_qkv[z];

    if (tid < 128) bias_sh[tid] = bias[n0 + tid];

    const uint32_t sbase = sptr(dsm);

    float acc[4][4][4];
    #pragma unroll
    for (int mi = 0; mi < 4; mi++)
        #pragma unroll
        for (int ni = 0; ni < 4; ni++)
            #pragma unroll
            for (int r = 0; r < 4; r++) acc[mi][ni][r] = 0.f;

    // ldmatrix address components (byte offsets inside a 128x128B tile)
    // A: groups {m0-7,c0},{m8-15,c0},{m0-7,c16},{m8-15,c16}
    const int a_row = warp_m * 64 + ((lane >> 3) & 1) * 8 + (lane & 7);
    const int a_cb0 = (lane >> 4) * 16;
    // B: groups {n0-7,c0},{n0-7,c16},{n8-15,c0},{n8-15,c16}
    const int b_row = warp_n * 32 + ((lane >> 4) & 1) * 8 + (lane & 7);
    const int b_cb0 = ((lane >> 3) & 1) * 16;

    // prologue: stages 0,1
    load_stage(sbase, 0, 0, m0, n0, tid, wh, wl);
    cp_commit();
    load_stage(sbase, 1, 1, m0, n0, tid, wh, wl);
    cp_commit();

    int slot_next = 2;
    for (int kt = 0; kt < NKT; ++kt) {
        cp_wait<1>();
        __syncthreads();
        if (kt + 2 < NKT) {
            load_stage(sbase, slot_next, kt + 2, m0, n0, tid, wh, wl);
            slot_next = (slot_next == 2) ? 0 : slot_next + 1;
        }
        cp_commit();

        const uint32_t abase = sbase + (uint32_t)(kt % 3) * STAGE_BYTES;
        const uint32_t bbase = abase + 16384;

        #pragma unroll
        for (int ks = 0; ks < 4; ks++) {
            uint32_t a[4][4], b[4][2];
            #pragma unroll
            for (int mi = 0; mi < 4; mi++) {
                uint32_t off = (uint32_t)((a_row + mi * 16) * 128 + ks * 32 + a_cb0);
                ldm_x4(a[mi][0], a[mi][1], a[mi][2], a[mi][3], abase + SWZ(off));
            }
            #pragma unroll
            for (int pr = 0; pr < 2; pr++) {
                uint32_t off = (uint32_t)((b_row + pr * 16) * 128 + ks * 32 + b_cb0);
                uint32_t r0, r1, r2, r3;
                ldm_x4(r0, r1, r2, r3, bbase + SWZ(off));
                b[pr * 2 + 0][0] = r0; b[pr * 2 + 0][1] = r1;
                b[pr * 2 + 1][0] = r2; b[pr * 2 + 1][1] = r3;
            }
            #pragma unroll
            for (int mi = 0; mi < 4; mi++)
                #pragma unroll
                for (int ni = 0; ni < 4; ni++)
                    mma_bf16(acc[mi][ni], a[mi], b[ni]);
        }
    }

    __syncthreads();

    // epilogue: c0,c1 -> (row, col..col+1), c2,c3 -> (row+8, ...)
    {
        const int row_base = m0 + warp_m * 64 + (lane >> 2);
        const int col_loc = warp_n * 32 + (lane & 3) * 2;
        #pragma unroll
        for (int mi = 0; mi < 4; mi++) {
            #pragma unroll
            for (int ni = 0; ni < 4; ni++) {
                const int col = col_loc + ni * 8;
                const float b0 = bias_sh[col], b1 = bias_sh[col + 1];
                float* p0 = out + (size_t)(row_base + mi * 16) * N_TOT + n0 + col;
                float* p1 = p0 + 8 * N_TOT;
                float2 v0 = {acc[mi][ni][0] + b0, acc[mi][ni][1] + b1};
                float2 v1 = {acc[mi][ni][2] + b0, acc[mi][ni][3] + b1};
                *(float2*)p0 = v0;
                *(float2*)p1 = v1;
            }
        }
    }
}

// ---------------- per-token attention ----------------
__global__ __launch_bounds__(256)
void attn_kernel(float* __restrict__ out)
{
    const int tok = blockIdx.x;
    __shared__ float qs[16 * 68];
    __shared__ float ks[16 * 68];
    __shared__ float vs[16 * 68];
    __shared__ float att[16 * 17];

    const int tid = threadIdx.x;
    const float* __restrict__ q = g_qkv[0] + (size_t)tok * 1024;
    const float* __restrict__ k = g_qkv[1] + (size_t)tok * 1024;
    const float* __restrict__ v = g_qkv[2] + (size_t)tok * 1024;

    {
        const int e = tid * 4;
        const int h = e >> 6;
        const int d = e & 63;
        *(float4*)&qs[h * 68 + d] = *(const float4*)(q + e);
        *(float4*)&ks[h * 68 + d] = *(const float4*)(k + e);
        *(float4*)&vs[h * 68 + d] = *(const float4*)(v + e);
    }
    __syncthreads();

    {
        const int h = tid >> 4;
        const int t = tid & 15;
        float s = 0.f;
        #pragma unroll
        for (int d4 = 0; d4 < 16; d4++) {
            float4 qv = *(const float4*)&qs[h * 68 + d4 * 4];
            float4 kv = *(const float4*)&ks[t * 68 + d4 * 4];
            s += qv.x * kv.x + qv.y * kv.y + qv.z * kv.z + qv.w * kv.w;
        }
        att[h * 17 + t] = s;
    }
    __syncthreads();

    {
        const int h = tid >> 4;
        const int dv = (tid & 15) * 4;
        float4 o = {0.f, 0.f, 0.f, 0.f};
        #pragma unroll
        for (int t = 0; t < 16; t++) {
            const float a = att[h * 17 + t];
            float4 vv = *(const float4*)&vs[t * 68 + dv];
            o.x += a * vv.x; o.y += a * vv.y; o.z += a * vv.z; o.w += a * vv.w;
        }
        *(float4*)(out + (size_t)tok * 1024 + h * 64 + dv) = o;
    }
}

extern "C" void kernel_launch(void* const* d_in, const int* in_sizes, int n_in,
                              void* d_out, int out_size)
{
    const float* x  = (const float*)d_in[0];
    const float* Wq = (const float*)d_in[1];
    const float* bq = (const float*)d_in[2];
    const float* Wk = (const float*)d_in[3];
    const float* bk = (const float*)d_in[4];
    const float* Wv = (const float*)d_in[5];
    const float* bv = (const float*)d_in[6];
    float* out = (float*)d_out;

    split_x_kernel<<<M_TOT * K_TOT / 1024, 256>>>(x);
    split_w_kernel<<<dim3(32, 32, 3), dim3(32, 32)>>>(Wq, Wk, Wv);

    cudaFuncSetAttribute(qkv_gemm_mma, cudaFuncAttributeMaxDynamicSharedMemorySize, SMEM_DYN);
    qkv_gemm_mma<<<dim3(8, 128, 3), 256, SMEM_DYN>>>(bq, bk, bv);

    attn_kernel<<<M_TOT, 256>>>(out);
}

// round 4
// speedup vs baseline: 3.3163x; 1.2947x over previous
#include <cuda_runtime.h>
#include <cuda_fp16.h>
#include <cstdint>

// Problem shape: B=4, S=4096, E=1024, H=16, D=64
#define M_TOT 16384
#define N_TOT 1024
#define K_TOT 1024

// ---------------- static device scratch ----------------
__device__ float g_qkv[3][(size_t)M_TOT * N_TOT];          // 192 MB
__device__ __half g_xh[(size_t)M_TOT * K_TOT];             // 32 MB  (fp16(x))
__device__ __half g_wh[3][(size_t)K_TOT * N_TOT];          // transposed [n][k], fp16(W)
__device__ __half g_wl[3][(size_t)K_TOT * N_TOT];          // fp16(W - wh)

// ---------------- PTX helpers (sm_80-compatible) ----------------
__device__ __forceinline__ uint32_t sptr(const void* p) {
    return (uint32_t)__cvta_generic_to_shared(p);
}
__device__ __forceinline__ void cpa16(uint32_t s, const void* g) {
    asm volatile("cp.async.cg.shared.global [%0], [%1], 16;" :: "r"(s), "l"(g) : "memory");
}
__device__ __forceinline__ void cp_commit() { asm volatile("cp.async.commit_group;" ::: "memory"); }
template <int N> __device__ __forceinline__ void cp_wait() {
    asm volatile("cp.async.wait_group %0;" :: "n"(N) : "memory");
}
__device__ __forceinline__ void ldm_x4(uint32_t& r0, uint32_t& r1, uint32_t& r2, uint32_t& r3,
                                       uint32_t addr) {
    asm volatile("ldmatrix.sync.aligned.m8n8.x4.shared.b16 {%0,%1,%2,%3}, [%4];"
                 : "=r"(r0), "=r"(r1), "=r"(r2), "=r"(r3) : "r"(addr));
}
__device__ __forceinline__ void mma_f16(float* c, const uint32_t* a, const uint32_t* b) {
    asm volatile(
        "mma.sync.aligned.m16n8k16.row.col.f32.f16.f16.f32 "
        "{%0,%1,%2,%3}, {%4,%5,%6,%7}, {%8,%9}, {%0,%1,%2,%3};"
        : "+f"(c[0]), "+f"(c[1]), "+f"(c[2]), "+f"(c[3])
        : "r"(a[0]), "r"(a[1]), "r"(a[2]), "r"(a[3]), "r"(b[0]), "r"(b[1]));
}

#define SWZ(o) ((o) ^ (((o) >> 3) & 0x70))

// ---------------- split kernels ----------------
__global__ __launch_bounds__(256)
void split_x_kernel(const float* __restrict__ x) {
    size_t i = ((size_t)blockIdx.x * 256 + threadIdx.x) * 4;
    float4 v = *(const float4*)(x + i);
    union { __half h[4]; uint2 u; } p;
    p.h[0] = __float2half_rn(v.x);
    p.h[1] = __float2half_rn(v.y);
    p.h[2] = __float2half_rn(v.z);
    p.h[3] = __float2half_rn(v.w);
    *(uint2*)(g_xh + i) = p.u;
}

// transpose + split W[k][n] -> Wh^T[n][k], Wl^T[n][k] (fp16 pair; wl uses subnormals)
__global__ __launch_bounds__(1024)
void split_w_kernel(const float* __restrict__ Wq, const float* __restrict__ Wk,
                    const float* __restrict__ Wv) {
    const int z = blockIdx.z;
    const float* __restrict__ W = (z == 0) ? Wq : (z == 1) ? Wk : Wv;
    __shared__ float tile[32][33];
    const int k0 = blockIdx.y * 32, n0 = blockIdx.x * 32;
    const int tx = threadIdx.x, ty = threadIdx.y;
    tile[ty][tx] = W[(size_t)(k0 + ty) * N_TOT + n0 + tx];
    __syncthreads();
    float f = tile[tx][ty];  // = W[k0+tx][n0+ty]
    __half hb = __float2half_rn(f);
    float r = f - __half2float(hb);
    size_t o = (size_t)(n0 + ty) * K_TOT + k0 + tx;
    g_wh[z][o] = hb;
    g_wl[z][o] = __float2half_rn(r);
}

// ---------------- fp16 2-term GEMM: out = xh@(wh+wl) + bias ----------------
// CTA 256x128, 512 threads (16 warps, warp tile 64x32), BK=64, 3-stage pipeline.
// Stage = A 32KB + Bh 16KB + Bl 16KB = 64KB. A fragments reused for both B terms.
static constexpr int STAGE_BYTES = 65536;
static constexpr uint32_t OFF_BH = 32768, OFF_BL = 49152;
static constexpr int SMEM_DYN = 3 * STAGE_BYTES;   // 192 KB
static constexpr int NKT = 16;                     // 1024 / 64

__device__ __forceinline__ void load_stage(uint32_t sb, int kt, int m0, int n0, int tid,
                                           const __half* __restrict__ wh,
                                           const __half* __restrict__ wl)
{
    const int kb = kt * 64;
    #pragma unroll
    for (int i = 0; i < 4; i++) {                 // A: 256 rows x 8 chunks
        int idx = tid + i * 512;
        int row = idx >> 3, c = idx & 7;
        uint32_t so = SWZ((uint32_t)(row * 128 + c * 16));
        cpa16(sb + so, g_xh + (((size_t)(m0 + row)) << 10) + kb + c * 8);
    }
    #pragma unroll
    for (int i = 0; i < 2; i++) {                 // Bh/Bl: 128 rows x 8 chunks each
        int idx = tid + i * 512;
        int row = idx >> 3, c = idx & 7;
        uint32_t so = SWZ((uint32_t)(row * 128 + c * 16));
        size_t go = (((size_t)(n0 + row)) << 10) + kb + c * 8;
        cpa16(sb + OFF_BH + so, wh + go);
        cpa16(sb + OFF_BL + so, wl + go);
    }
}

__global__ __launch_bounds__(512, 1)
void qkv_gemm_mma(const float* __restrict__ bq, const float* __restrict__ bk,
                  const float* __restrict__ bv)
{
    extern __shared__ __align__(16) char dsm[];
    __shared__ float bias_sh[128];

    const int tid = threadIdx.x;
    const int lane = tid & 31;
    const int wid = tid >> 5;
    const int warp_m = wid >> 2;       // 0..3 -> 64-row quarters of 256
    const int warp_n = wid & 3;        // 0..3 -> 32-col quarters of 128
    const int z = blockIdx.z;
    const int n0 = blockIdx.x * 128;
    const int m0 = blockIdx.y * 256;

    const __half* __restrict__ wh = g_wh[z];
    const __half* __restrict__ wl = g_wl[z];
    const float* __restrict__ bias = (z == 0) ? bq : (z == 1) ? bk : bv;
    float* __restrict__ out = g_qkv[z];

    if (tid < 128) bias_sh[tid] = bias[n0 + tid];

    const uint32_t sbase = sptr(dsm);

    float acc[4][4][4];
    #pragma unroll
    for (int mi = 0; mi < 4; mi++)
        #pragma unroll
        for (int ni = 0; ni < 4; ni++)
            #pragma unroll
            for (int r = 0; r < 4; r++) acc[mi][ni][r] = 0.f;

    // ldmatrix address components
    const int a_row = warp_m * 64 + ((lane >> 3) & 1) * 8 + (lane & 7);
    const int a_cb0 = (lane >> 4) * 16;
    const int b_row = warp_n * 32 + ((lane >> 4) & 1) * 8 + (lane & 7);
    const int b_cb0 = ((lane >> 3) & 1) * 16;

    // prologue: stages 0,1
    load_stage(sbase, 0, m0, n0, tid, wh, wl);
    cp_commit();
    load_stage(sbase + STAGE_BYTES, 1, m0, n0, tid, wh, wl);
    cp_commit();

    for (int kt = 0; kt < NKT; ++kt) {
        cp_wait<1>();
        __syncthreads();
        if (kt + 2 < NKT)
            load_stage(sbase + (uint32_t)((kt + 2) % 3) * STAGE_BYTES, kt + 2, m0, n0, tid, wh, wl);
        cp_commit();   // always commit so group counting stays aligned

        const uint32_t abase = sbase + (uint32_t)(kt % 3) * STAGE_BYTES;

        #pragma unroll
        for (int ks = 0; ks < 4; ks++) {
            uint32_t a[4][4];
            #pragma unroll
            for (int mi = 0; mi < 4; mi++) {
                uint32_t off = (uint32_t)((a_row + mi * 16) * 128 + ks * 32 + a_cb0);
                ldm_x4(a[mi][0], a[mi][1], a[mi][2], a[mi][3], abase + SWZ(off));
            }
            // ---- Bh pass ----
            {
                uint32_t b[4][2];
                #pragma unroll
                for (int pr = 0; pr < 2; pr++) {
                    uint32_t off = (uint32_t)((b_row + pr * 16) * 128 + ks * 32 + b_cb0);
                    uint32_t r0, r1, r2, r3;
                    ldm_x4(r0, r1, r2, r3, abase + OFF_BH + SWZ(off));
                    b[pr * 2 + 0][0] = r0; b[pr * 2 + 0][1] = r1;
                    b[pr * 2 + 1][0] = r2; b[pr * 2 + 1][1] = r3;
                }
                #pragma unroll
                for (int mi = 0; mi < 4; mi++)
                    #pragma unroll
                    for (int ni = 0; ni < 4; ni++)
                        mma_f16(acc[mi][ni], a[mi], b[ni]);
            }
            // ---- Bl pass (same A fragments) ----
            {
                uint32_t b[4][2];
                #pragma unroll
                for (int pr = 0; pr < 2; pr++) {
                    uint32_t off = (uint32_t)((b_row + pr * 16) * 128 + ks * 32 + b_cb0);
                    uint32_t r0, r1, r2, r3;
                    ldm_x4(r0, r1, r2, r3, abase + OFF_BL + SWZ(off));
                    b[pr * 2 + 0][0] = r0; b[pr * 2 + 0][1] = r1;
                    b[pr * 2 + 1][0] = r2; b[pr * 2 + 1][1] = r3;
                }
                #pragma unroll
                for (int mi = 0; mi < 4; mi++)
                    #pragma unroll
                    for (int ni = 0; ni < 4; ni++)
                        mma_f16(acc[mi][ni], a[mi], b[ni]);
            }
        }
    }

    __syncthreads();

    // epilogue
    {
        const int row_base = m0 + warp_m * 64 + (lane >> 2);
        const int col_loc = warp_n * 32 + (lane & 3) * 2;
        #pragma unroll
        for (int mi = 0; mi < 4; mi++) {
            #pragma unroll
            for (int ni = 0; ni < 4; ni++) {
                const int col = col_loc + ni * 8;
                const float b0 = bias_sh[col], b1 = bias_sh[col + 1];
                float* p0 = out + (size_t)(row_base + mi * 16) * N_TOT + n0 + col;
                float* p1 = p0 + 8 * N_TOT;
                float2 v0 = {acc[mi][ni][0] + b0, acc[mi][ni][1] + b1};
                float2 v1 = {acc[mi][ni][2] + b0, acc[mi][ni][3] + b1};
                *(float2*)p0 = v0;
                *(float2*)p1 = v1;
            }
        }
    }
}

// ---------------- per-token attention ----------------
__global__ __launch_bounds__(256)
void attn_kernel(float* __restrict__ out)
{
    const int tok = blockIdx.x;
    __shared__ float qs[16 * 68];
    __shared__ float ks[16 * 68];
    __shared__ float vs[16 * 68];
    __shared__ float att[16 * 17];

    const int tid = threadIdx.x;
    const float* __restrict__ q = g_qkv[0] + (size_t)tok * 1024;
    const float* __restrict__ k = g_qkv[1] + (size_t)tok * 1024;
    const float* __restrict__ v = g_qkv[2] + (size_t)tok * 1024;

    {
        const int e = tid * 4;
        const int h = e >> 6;
        const int d = e & 63;
        *(float4*)&qs[h * 68 + d] = *(const float4*)(q + e);
        *(float4*)&ks[h * 68 + d] = *(const float4*)(k + e);
        *(float4*)&vs[h * 68 + d] = *(const float4*)(v + e);
    }
    __syncthreads();

    {
        const int h = tid >> 4;
        const int t = tid & 15;
        float s = 0.f;
        #pragma unroll
        for (int d4 = 0; d4 < 16; d4++) {
            float4 qv = *(const float4*)&qs[h * 68 + d4 * 4];
            float4 kv = *(const float4*)&ks[t * 68 + d4 * 4];
            s += qv.x * kv.x + qv.y * kv.y + qv.z * kv.z + qv.w * kv.w;
        }
        att[h * 17 + t] = s;
    }
    __syncthreads();

    {
        const int h = tid >> 4;
        const int dv = (tid & 15) * 4;
        float4 o = {0.f, 0.f, 0.f, 0.f};
        #pragma unroll
        for (int t = 0; t < 16; t++) {
            const float a = att[h * 17 + t];
            float4 vv = *(const float4*)&vs[t * 68 + dv];
            o.x += a * vv.x; o.y += a * vv.y; o.z += a * vv.z; o.w += a * vv.w;
        }
        *(float4*)(out + (size_t)tok * 1024 + h * 64 + dv) = o;
    }
}

extern "C" void kernel_launch(void* const* d_in, const int* in_sizes, int n_in,
                              void* d_out, int out_size)
{
    const float* x  = (const float*)d_in[0];
    const float* Wq = (const float*)d_in[1];
    const float* bq = (const float*)d_in[2];
    const float* Wk = (const float*)d_in[3];
    const float* bk = (const float*)d_in[4];
    const float* Wv = (const float*)d_in[5];
    const float* bv = (const float*)d_in[6];
    float* out = (float*)d_out;

    split_x_kernel<<<M_TOT * K_TOT / 1024, 256>>>(x);
    split_w_kernel<<<dim3(32, 32, 3), dim3(32, 32)>>>(Wq, Wk, Wv);

    cudaFuncSetAttribute(qkv_gemm_mma, cudaFuncAttributeMaxDynamicSharedMemorySize, SMEM_DYN);
    qkv_gemm_mma<<<dim3(8, 64, 3), 512, SMEM_DYN>>>(bq, bk, bv);

    attn_kernel<<<M_TOT, 256>>>(out);
}

// round 5
// speedup vs baseline: 5.1123x; 1.5416x over previous
#include <cuda_runtime.h>
#include <cuda_fp16.h>
#include <cstdint>

// Problem shape: B=4, S=4096, E=1024, H=16, D=64
#define M_TOT 16384
#define N_TOT 1024
#define K_TOT 1024

// ---------------- static device scratch ----------------
__device__ float g_qkv[3][(size_t)M_TOT * N_TOT];          // 192 MB
__device__ __half g_xh[(size_t)M_TOT * K_TOT];             // 32 MB  (fp16(x))
__device__ __half g_wh[3][(size_t)K_TOT * N_TOT];          // transposed [n][k], fp16(W)

// ---------------- PTX helpers (sm_80-compatible) ----------------
__device__ __forceinline__ uint32_t sptr(const void* p) {
    return (uint32_t)__cvta_generic_to_shared(p);
}
__device__ __forceinline__ void cpa16(uint32_t s, const void* g) {
    asm volatile("cp.async.cg.shared.global [%0], [%1], 16;" :: "r"(s), "l"(g) : "memory");
}
__device__ __forceinline__ void cp_commit() { asm volatile("cp.async.commit_group;" ::: "memory"); }
template <int N> __device__ __forceinline__ void cp_wait() {
    asm volatile("cp.async.wait_group %0;" :: "n"(N) : "memory");
}
__device__ __forceinline__ void ldm_x4(uint32_t& r0, uint32_t& r1, uint32_t& r2, uint32_t& r3,
                                       uint32_t addr) {
    asm volatile("ldmatrix.sync.aligned.m8n8.x4.shared.b16 {%0,%1,%2,%3}, [%4];"
                 : "=r"(r0), "=r"(r1), "=r"(r2), "=r"(r3) : "r"(addr));
}
__device__ __forceinline__ void mma_f16(float* c, const uint32_t* a, const uint32_t* b) {
    asm volatile(
        "mma.sync.aligned.m16n8k16.row.col.f32.f16.f16.f32 "
        "{%0,%1,%2,%3}, {%4,%5,%6,%7}, {%8,%9}, {%0,%1,%2,%3};"
        : "+f"(c[0]), "+f"(c[1]), "+f"(c[2]), "+f"(c[3])
        : "r"(a[0]), "r"(a[1]), "r"(a[2]), "r"(a[3]), "r"(b[0]), "r"(b[1]));
}

#define SWZ(o) ((o) ^ (((o) >> 3) & 0x70))

// ---------------- convert kernels ----------------
__global__ __launch_bounds__(256)
void split_x_kernel(const float* __restrict__ x) {
    size_t i = ((size_t)blockIdx.x * 256 + threadIdx.x) * 8;
    float4 v0 = *(const float4*)(x + i);
    float4 v1 = *(const float4*)(x + i + 4);
    union { __half h[8]; uint4 u; } p;
    p.h[0] = __float2half_rn(v0.x); p.h[1] = __float2half_rn(v0.y);
    p.h[2] = __float2half_rn(v0.z); p.h[3] = __float2half_rn(v0.w);
    p.h[4] = __float2half_rn(v1.x); p.h[5] = __float2half_rn(v1.y);
    p.h[6] = __float2half_rn(v1.z); p.h[7] = __float2half_rn(v1.w);
    *(uint4*)(g_xh + i) = p.u;
}

// transpose + convert W[k][n] -> Wh^T[n][k]
__global__ __launch_bounds__(1024)
void split_w_kernel(const float* __restrict__ Wq, const float* __restrict__ Wk,
                    const float* __restrict__ Wv) {
    const int z = blockIdx.z;
    const float* __restrict__ W = (z == 0) ? Wq : (z == 1) ? Wk : Wv;
    __shared__ float tile[32][33];
    const int k0 = blockIdx.y * 32, n0 = blockIdx.x * 32;
    const int tx = threadIdx.x, ty = threadIdx.y;
    tile[ty][tx] = W[(size_t)(k0 + ty) * N_TOT + n0 + tx];
    __syncthreads();
    g_wh[z][(size_t)(n0 + ty) * K_TOT + k0 + tx] = __float2half_rn(tile[tx][ty]);
}

// ---------------- fp16 GEMM: out = xh@wh + bias ----------------
// CTA 256x128, 512 threads (16 warps, warp tile 64x32), BK=64, 4-stage pipeline.
// Stage = A 32KB + B 16KB = 48KB. 192 KB total smem.
static constexpr int STAGE_BYTES = 49152;
static constexpr uint32_t OFF_B = 32768;
static constexpr int NSTAGE = 4;
static constexpr int SMEM_DYN = NSTAGE * STAGE_BYTES;   // 192 KB
static constexpr int NKT = 16;                          // 1024 / 64

__device__ __forceinline__ void load_stage(uint32_t sb, int kt, int m0, int n0, int tid,
                                           const __half* __restrict__ wh)
{
    const int kb = kt * 64;
    #pragma unroll
    for (int i = 0; i < 4; i++) {                 // A: 256 rows x 8 chunks of 16B
        int idx = tid + i * 512;
        int row = idx >> 3, c = idx & 7;
        uint32_t so = SWZ((uint32_t)(row * 128 + c * 16));
        cpa16(sb + so, g_xh + (((size_t)(m0 + row)) << 10) + kb + c * 8);
    }
    #pragma unroll
    for (int i = 0; i < 2; i++) {                 // B: 128 rows x 8 chunks
        int idx = tid + i * 512;
        int row = idx >> 3, c = idx & 7;
        uint32_t so = SWZ((uint32_t)(row * 128 + c * 16));
        cpa16(sb + OFF_B + so, wh + (((size_t)(n0 + row)) << 10) + kb + c * 8);
    }
}

__global__ __launch_bounds__(512, 1)
void qkv_gemm_mma(const float* __restrict__ bq, const float* __restrict__ bk,
                  const float* __restrict__ bv)
{
    extern __shared__ __align__(16) char dsm[];
    __shared__ float bias_sh[128];

    const int tid = threadIdx.x;
    const int lane = tid & 31;
    const int wid = tid >> 5;
    const int warp_m = wid >> 2;       // 0..3 -> 64-row quarters of 256
    const int warp_n = wid & 3;        // 0..3 -> 32-col quarters of 128
    const int z = blockIdx.z;
    const int n0 = blockIdx.x * 128;
    const int m0 = blockIdx.y * 256;

    const __half* __restrict__ wh = g_wh[z];
    const float* __restrict__ bias = (z == 0) ? bq : (z == 1) ? bk : bv;
    float* __restrict__ out = g_qkv[z];

    if (tid < 128) bias_sh[tid] = bias[n0 + tid];

    const uint32_t sbase = sptr(dsm);

    float acc[4][4][4];
    #pragma unroll
    for (int mi = 0; mi < 4; mi++)
        #pragma unroll
        for (int ni = 0; ni < 4; ni++)
            #pragma unroll
            for (int r = 0; r < 4; r++) acc[mi][ni][r] = 0.f;

    const int a_row = warp_m * 64 + ((lane >> 3) & 1) * 8 + (lane & 7);
    const int a_cb0 = (lane >> 4) * 16;
    const int b_row = warp_n * 32 + ((lane >> 4) & 1) * 8 + (lane & 7);
    const int b_cb0 = ((lane >> 3) & 1) * 16;

    // prologue: stages 0..2
    load_stage(sbase, 0, m0, n0, tid, wh);
    cp_commit();
    load_stage(sbase + STAGE_BYTES, 1, m0, n0, tid, wh);
    cp_commit();
    load_stage(sbase + 2 * STAGE_BYTES, 2, m0, n0, tid, wh);
    cp_commit();

    for (int kt = 0; kt < NKT; ++kt) {
        cp_wait<2>();
        __syncthreads();
        if (kt + 3 < NKT)
            load_stage(sbase + (uint32_t)((kt + 3) % NSTAGE) * STAGE_BYTES, kt + 3, m0, n0, tid, wh);
        cp_commit();   // keep group counting aligned

        const uint32_t abase = sbase + (uint32_t)(kt % NSTAGE) * STAGE_BYTES;

        #pragma unroll
        for (int ks = 0; ks < 4; ks++) {
            uint32_t a[4][4], b[4][2];
            #pragma unroll
            for (int mi = 0; mi < 4; mi++) {
                uint32_t off = (uint32_t)((a_row + mi * 16) * 128 + ks * 32 + a_cb0);
                ldm_x4(a[mi][0], a[mi][1], a[mi][2], a[mi][3], abase + SWZ(off));
            }
            #pragma unroll
            for (int pr = 0; pr < 2; pr++) {
                uint32_t off = (uint32_t)((b_row + pr * 16) * 128 + ks * 32 + b_cb0);
                uint32_t r0, r1, r2, r3;
                ldm_x4(r0, r1, r2, r3, abase + OFF_B + SWZ(off));
                b[pr * 2 + 0][0] = r0; b[pr * 2 + 0][1] = r1;
                b[pr * 2 + 1][0] = r2; b[pr * 2 + 1][1] = r3;
            }
            #pragma unroll
            for (int mi = 0; mi < 4; mi++)
                #pragma unroll
                for (int ni = 0; ni < 4; ni++)
                    mma_f16(acc[mi][ni], a[mi], b[ni]);
        }
    }

    __syncthreads();

    // epilogue
    {
        const int row_base = m0 + warp_m * 64 + (lane >> 2);
        const int col_loc = warp_n * 32 + (lane & 3) * 2;
        #pragma unroll
        for (int mi = 0; mi < 4; mi++) {
            #pragma unroll
            for (int ni = 0; ni < 4; ni++) {
                const int col = col_loc + ni * 8;
                const float b0 = bias_sh[col], b1 = bias_sh[col + 1];
                float* p0 = out + (size_t)(row_base + mi * 16) * N_TOT + n0 + col;
                float* p1 = p0 + 8 * N_TOT;
                float2 v0 = {acc[mi][ni][0] + b0, acc[mi][ni][1] + b1};
                float2 v1 = {acc[mi][ni][2] + b0, acc[mi][ni][3] + b1};
                *(float2*)p0 = v0;
                *(float2*)p1 = v1;
            }
        }
    }
}

// ---------------- per-token attention ----------------
__global__ __launch_bounds__(256)
void attn_kernel(float* __restrict__ out)
{
    const int tok = blockIdx.x;
    __shared__ float qs[16 * 68];
    __shared__ float ks[16 * 68];
    __shared__ float vs[16 * 68];
    __shared__ float att[16 * 17];

    const int tid = threadIdx.x;
    const float* __restrict__ q = g_qkv[0] + (size_t)tok * 1024;
    const float* __restrict__ k = g_qkv[1] + (size_t)tok * 1024;
    const float* __restrict__ v = g_qkv[2] + (size_t)tok * 1024;

    {
        const int e = tid * 4;
        const int h = e >> 6;
        const int d = e & 63;
        *(float4*)&qs[h * 68 + d] = *(const float4*)(q + e);
        *(float4*)&ks[h * 68 + d] = *(const float4*)(k + e);
        *(float4*)&vs[h * 68 + d] = *(const float4*)(v + e);
    }
    __syncthreads();

    {
        const int h = tid >> 4;
        const int t = tid & 15;
        float s = 0.f;
        #pragma unroll
        for (int d4 = 0; d4 < 16; d4++) {
            float4 qv = *(const float4*)&qs[h * 68 + d4 * 4];
            float4 kv = *(const float4*)&ks[t * 68 + d4 * 4];
            s += qv.x * kv.x + qv.y * kv.y + qv.z * kv.z + qv.w * kv.w;
        }
        att[h * 17 + t] = s;
    }
    __syncthreads();

    {
        const int h = tid >> 4;
        const int dv = (tid & 15) * 4;
        float4 o = {0.f, 0.f, 0.f, 0.f};
        #pragma unroll
        for (int t = 0; t < 16; t++) {
            const float a = att[h * 17 + t];
            float4 vv = *(const float4*)&vs[t * 68 + dv];
            o.x += a * vv.x; o.y += a * vv.y; o.z += a * vv.z; o.w += a * vv.w;
        }
        *(float4*)(out + (size_t)tok * 1024 + h * 64 + dv) = o;
    }
}

extern "C" void kernel_launch(void* const* d_in, const int* in_sizes, int n_in,
                              void* d_out, int out_size)
{
    const float* x  = (const float*)d_in[0];
    const float* Wq = (const float*)d_in[1];
    const float* bq = (const float*)d_in[2];
    const float* Wk = (const float*)d_in[3];
    const float* bk = (const float*)d_in[4];
    const float* Wv = (const float*)d_in[5];
    const float* bv = (const float*)d_in[6];
    float* out = (float*)d_out;

    split_x_kernel<<<M_TOT * K_TOT / 2048, 256>>>(x);
    split_w_kernel<<<dim3(32, 32, 3), dim3(32, 32)>>>(Wq, Wk, Wv);

    cudaFuncSetAttribute(qkv_gemm_mma, cudaFuncAttributeMaxDynamicSharedMemorySize, SMEM_DYN);
    qkv_gemm_mma<<<dim3(8, 64, 3), 512, SMEM_DYN>>>(bq, bk, bv);

    attn_kernel<<<M_TOT, 256>>>(out);
}

// round 6
// speedup vs baseline: 6.2783x; 1.2281x over previous
#include <cuda_runtime.h>
#include <cuda_fp16.h>
#include <cstdint>

// Problem shape: B=4, S=4096, E=1024, H=16, D=64
#define M_TOT 16384
#define N_TOT 1024
#define K_TOT 1024

// ---------------- static device scratch ----------------
__device__ __half g_qkvh[3][(size_t)M_TOT * N_TOT];        // 96 MB (fp16 q,k,v)
__device__ __half g_xh[(size_t)M_TOT * K_TOT];             // 32 MB  (fp16(x))
__device__ __half g_wh[3][(size_t)K_TOT * N_TOT];          // transposed [n][k], fp16(W)

// ---------------- PTX helpers (sm_80-compatible) ----------------
__device__ __forceinline__ uint32_t sptr(const void* p) {
    return (uint32_t)__cvta_generic_to_shared(p);
}
__device__ __forceinline__ void cpa16(uint32_t s, const void* g) {
    asm volatile("cp.async.cg.shared.global [%0], [%1], 16;" :: "r"(s), "l"(g) : "memory");
}
__device__ __forceinline__ void cp_commit() { asm volatile("cp.async.commit_group;" ::: "memory"); }
template <int N> __device__ __forceinline__ void cp_wait() {
    asm volatile("cp.async.wait_group %0;" :: "n"(N) : "memory");
}
__device__ __forceinline__ void ldm_x4(uint32_t& r0, uint32_t& r1, uint32_t& r2, uint32_t& r3,
                                       uint32_t addr) {
    asm volatile("ldmatrix.sync.aligned.m8n8.x4.shared.b16 {%0,%1,%2,%3}, [%4];"
                 : "=r"(r0), "=r"(r1), "=r"(r2), "=r"(r3) : "r"(addr));
}
__device__ __forceinline__ void ldm_x4t(uint32_t& r0, uint32_t& r1, uint32_t& r2, uint32_t& r3,
                                        uint32_t addr) {
    asm volatile("ldmatrix.sync.aligned.m8n8.x4.trans.shared.b16 {%0,%1,%2,%3}, [%4];"
                 : "=r"(r0), "=r"(r1), "=r"(r2), "=r"(r3) : "r"(addr));
}
__device__ __forceinline__ void mma_f16(float* c, const uint32_t* a, const uint32_t* b) {
    asm volatile(
        "mma.sync.aligned.m16n8k16.row.col.f32.f16.f16.f32 "
        "{%0,%1,%2,%3}, {%4,%5,%6,%7}, {%8,%9}, {%0,%1,%2,%3};"
        : "+f"(c[0]), "+f"(c[1]), "+f"(c[2]), "+f"(c[3])
        : "r"(a[0]), "r"(a[1]), "r"(a[2]), "r"(a[3]), "r"(b[0]), "r"(b[1]));
}

#define SWZ(o) ((o) ^ (((o) >> 3) & 0x70))

// ---------------- convert kernels ----------------
__global__ __launch_bounds__(256)
void split_x_kernel(const float* __restrict__ x) {
    size_t i = ((size_t)blockIdx.x * 256 + threadIdx.x) * 8;
    float4 v0 = *(const float4*)(x + i);
    float4 v1 = *(const float4*)(x + i + 4);
    union { __half h[8]; uint4 u; } p;
    p.h[0] = __float2half_rn(v0.x); p.h[1] = __float2half_rn(v0.y);
    p.h[2] = __float2half_rn(v0.z); p.h[3] = __float2half_rn(v0.w);
    p.h[4] = __float2half_rn(v1.x); p.h[5] = __float2half_rn(v1.y);
    p.h[6] = __float2half_rn(v1.z); p.h[7] = __float2half_rn(v1.w);
    *(uint4*)(g_xh + i) = p.u;
}

// transpose + convert W[k][n] -> Wh^T[n][k]
__global__ __launch_bounds__(1024)
void split_w_kernel(const float* __restrict__ Wq, const float* __restrict__ Wk,
                    const float* __restrict__ Wv) {
    const int z = blockIdx.z;
    const float* __restrict__ W = (z == 0) ? Wq : (z == 1) ? Wk : Wv;
    __shared__ float tile[32][33];
    const int k0 = blockIdx.y * 32, n0 = blockIdx.x * 32;
    const int tx = threadIdx.x, ty = threadIdx.y;
    tile[ty][tx] = W[(size_t)(k0 + ty) * N_TOT + n0 + tx];
    __syncthreads();
    g_wh[z][(size_t)(n0 + ty) * K_TOT + k0 + tx] = __float2half_rn(tile[tx][ty]);
}

// ---------------- fp16 GEMM: qkv = xh@wh + bias (fp16 output) ----------------
// CTA 256x128, 512 threads (16 warps, warp tile 64x32), BK=64, 4-stage pipeline.
static constexpr int STAGE_BYTES = 49152;
static constexpr uint32_t OFF_B = 32768;
static constexpr int NSTAGE = 4;
static constexpr int SMEM_DYN = NSTAGE * STAGE_BYTES;   // 192 KB
static constexpr int NKT = 16;                          // 1024 / 64

__device__ __forceinline__ void load_stage(uint32_t sb, int kt, int m0, int n0, int tid,
                                           const __half* __restrict__ wh)
{
    const int kb = kt * 64;
    #pragma unroll
    for (int i = 0; i < 4; i++) {                 // A: 256 rows x 8 chunks of 16B
        int idx = tid + i * 512;
        int row = idx >> 3, c = idx & 7;
        uint32_t so = SWZ((uint32_t)(row * 128 + c * 16));
        cpa16(sb + so, g_xh + (((size_t)(m0 + row)) << 10) + kb + c * 8);
    }
    #pragma unroll
    for (int i = 0; i < 2; i++) {                 // B: 128 rows x 8 chunks
        int idx = tid + i * 512;
        int row = idx >> 3, c = idx & 7;
        uint32_t so = SWZ((uint32_t)(row * 128 + c * 16));
        cpa16(sb + OFF_B + so, wh + (((size_t)(n0 + row)) << 10) + kb + c * 8);
    }
}

__global__ __launch_bounds__(512, 1)
void qkv_gemm_mma(const float* __restrict__ bq, const float* __restrict__ bk,
                  const float* __restrict__ bv)
{
    extern __shared__ __align__(16) char dsm[];
    __shared__ float bias_sh[128];

    const int tid = threadIdx.x;
    const int lane = tid & 31;
    const int wid = tid >> 5;
    const int warp_m = wid >> 2;
    const int warp_n = wid & 3;
    const int z = blockIdx.z;
    const int n0 = blockIdx.x * 128;
    const int m0 = blockIdx.y * 256;

    const __half* __restrict__ wh = g_wh[z];
    const float* __restrict__ bias = (z == 0) ? bq : (z == 1) ? bk : bv;
    __half* __restrict__ out = g_qkvh[z];

    if (tid < 128) bias_sh[tid] = bias[n0 + tid];

    const uint32_t sbase = sptr(dsm);

    float acc[4][4][4];
    #pragma unroll
    for (int mi = 0; mi < 4; mi++)
        #pragma unroll
        for (int ni = 0; ni < 4; ni++)
            #pragma unroll
            for (int r = 0; r < 4; r++) acc[mi][ni][r] = 0.f;

    const int a_row = warp_m * 64 + ((lane >> 3) & 1) * 8 + (lane & 7);
    const int a_cb0 = (lane >> 4) * 16;
    const int b_row = warp_n * 32 + ((lane >> 4) & 1) * 8 + (lane & 7);
    const int b_cb0 = ((lane >> 3) & 1) * 16;

    load_stage(sbase, 0, m0, n0, tid, wh);
    cp_commit();
    load_stage(sbase + STAGE_BYTES, 1, m0, n0, tid, wh);
    cp_commit();
    load_stage(sbase + 2 * STAGE_BYTES, 2, m0, n0, tid, wh);
    cp_commit();

    for (int kt = 0; kt < NKT; ++kt) {
        cp_wait<2>();
        __syncthreads();
        if (kt + 3 < NKT)
            load_stage(sbase + (uint32_t)((kt + 3) % NSTAGE) * STAGE_BYTES, kt + 3, m0, n0, tid, wh);
        cp_commit();

        const uint32_t abase = sbase + (uint32_t)(kt % NSTAGE) * STAGE_BYTES;

        #pragma unroll
        for (int ks = 0; ks < 4; ks++) {
            uint32_t a[4][4], b[4][2];
            #pragma unroll
            for (int mi = 0; mi < 4; mi++) {
                uint32_t off = (uint32_t)((a_row + mi * 16) * 128 + ks * 32 + a_cb0);
                ldm_x4(a[mi][0], a[mi][1], a[mi][2], a[mi][3], abase + SWZ(off));
            }
            #pragma unroll
            for (int pr = 0; pr < 2; pr++) {
                uint32_t off = (uint32_t)((b_row + pr * 16) * 128 + ks * 32 + b_cb0);
                uint32_t r0, r1, r2, r3;
                ldm_x4(r0, r1, r2, r3, abase + OFF_B + SWZ(off));
                b[pr * 2 + 0][0] = r0; b[pr * 2 + 0][1] = r1;
                b[pr * 2 + 1][0] = r2; b[pr * 2 + 1][1] = r3;
            }
            #pragma unroll
            for (int mi = 0; mi < 4; mi++)
                #pragma unroll
                for (int ni = 0; ni < 4; ni++)
                    mma_f16(acc[mi][ni], a[mi], b[ni]);
        }
    }

    __syncthreads();

    // epilogue: fp16 output, half2 stores
    {
        const int row_base = m0 + warp_m * 64 + (lane >> 2);
        const int col_loc = warp_n * 32 + (lane & 3) * 2;
        #pragma unroll
        for (int mi = 0; mi < 4; mi++) {
            #pragma unroll
            for (int ni = 0; ni < 4; ni++) {
                const int col = col_loc + ni * 8;
                const float b0 = bias_sh[col], b1 = bias_sh[col + 1];
                __half* p0 = out + (size_t)(row_base + mi * 16) * N_TOT + n0 + col;
                __half* p1 = p0 + 8 * N_TOT;
                *(__half2*)p0 = __floats2half2_rn(acc[mi][ni][0] + b0, acc[mi][ni][1] + b1);
                *(__half2*)p1 = __floats2half2_rn(acc[mi][ni][2] + b0, acc[mi][ni][3] + b1);
            }
        }
    }
}

// ---------------- tensor-core per-token attention ----------------
// One warp per token. q,k,v fp16 16x64 each (2KB, 128B swizzled rows).
// att = q@k^T (8 HMMA), convert C-frag -> A-frag in registers, out = att@v (8 HMMA).
__global__ __launch_bounds__(256)
void attn_mma(float* __restrict__ out)
{
    __shared__ __align__(128) char sm[8 * 6144];   // 48 KB: 8 tokens x (q|k|v)

    const int lane = threadIdx.x & 31;
    const int wid = threadIdx.x >> 5;
    const int token = blockIdx.x * 8 + wid;
    const uint32_t tb = sptr(sm) + (uint32_t)wid * 6144;

    // load this warp's token: 3 matrices x 16 rows x 8 chunks = 384 cpa16, 12/lane
    #pragma unroll
    for (int j = 0; j < 12; j++) {
        int idx = lane + j * 32;          // 0..383
        int mat = idx >> 7;               // 0..2
        int rem = idx & 127;
        int r = rem >> 3, c = rem & 7;
        cpa16(tb + (uint32_t)mat * 2048 + SWZ((uint32_t)(r * 128 + c * 16)),
              g_qkvh[mat] + ((size_t)token << 10) + r * 64 + c * 8);
    }
    cp_commit();
    cp_wait<0>();
    __syncwarp();

    const int a_row = ((lane >> 3) & 1) * 8 + (lane & 7);
    const int a_cb = (lane >> 4) * 16;
    const int b_row = ((lane >> 4) & 1) * 8 + (lane & 7);
    const int b_cb = ((lane >> 3) & 1) * 16;
    // trans-load rows for v (B row-major): groups {t0-7,d0-7},{t8-15,d0-7},{t0-7,d8-15},{t8-15,d8-15}
    const int v_row = ((lane >> 3) & 1) * 8 + (lane & 7);
    const int v_cb = (lane >> 4) * 16;

    // phase A: att = q @ k^T  (C covers att[16 x 16], two n8 tiles)
    float attc[2][4] = {{0.f, 0.f, 0.f, 0.f}, {0.f, 0.f, 0.f, 0.f}};
    #pragma unroll
    for (int kc = 0; kc < 4; kc++) {
        uint32_t a[4];
        ldm_x4(a[0], a[1], a[2], a[3], tb + SWZ((uint32_t)(a_row * 128 + kc * 32 + a_cb)));
        uint32_t r0, r1, r2, r3;
        ldm_x4(r0, r1, r2, r3, tb + 2048 + SWZ((uint32_t)(b_row * 128 + kc * 32 + b_cb)));
        uint32_t blo[2] = {r0, r1}, bhi[2] = {r2, r3};
        mma_f16(attc[0], a, blo);
        mma_f16(attc[1], a, bhi);
    }

    // convert att C-frag (fp32) -> A-frag (fp16) in registers
    uint32_t aa[4];
    {
        __half2 h0 = __floats2half2_rn(attc[0][0], attc[0][1]);  // (row, k0..1)
        __half2 h1 = __floats2half2_rn(attc[0][2], attc[0][3]);  // (row+8, k0..1)
        __half2 h2 = __floats2half2_rn(attc[1][0], attc[1][1]);  // (row, k8..9)
        __half2 h3 = __floats2half2_rn(attc[1][2], attc[1][3]);  // (row+8, k8..9)
        aa[0] = *(uint32_t*)&h0;
        aa[1] = *(uint32_t*)&h1;
        aa[2] = *(uint32_t*)&h2;
        aa[3] = *(uint32_t*)&h3;
    }

    // phase B: out = att @ v ; v row-major [t][d] loaded with ldmatrix.trans
    float* __restrict__ op = out + ((size_t)token << 10);
    const int row = lane >> 2;
    const int cl = (lane & 3) * 2;
    #pragma unroll
    for (int dc = 0; dc < 4; dc++) {
        uint32_t r0, r1, r2, r3;
        ldm_x4t(r0, r1, r2, r3, tb + 4096 + SWZ((uint32_t)(v_row * 128 + dc * 32 + v_cb)));
        uint32_t blo[2] = {r0, r1}, bhi[2] = {r2, r3};
        float oc0[4] = {0.f, 0.f, 0.f, 0.f};
        float oc1[4] = {0.f, 0.f, 0.f, 0.f};
        mma_f16(oc0, aa, blo);
        mma_f16(oc1, aa, bhi);
        // store: out[h=row][d = dc*16 + nt*8 + cl]
        float* p = op + row * 64 + dc * 16 + cl;
        *(float2*)(p) = make_float2(oc0[0], oc0[1]);
        *(float2*)(p + 8 * 64) = make_float2(oc0[2], oc0[3]);
        *(float2*)(p + 8) = make_float2(oc1[0], oc1[1]);
        *(float2*)(p + 8 * 64 + 8) = make_float2(oc1[2], oc1[3]);
    }
}

extern "C" void kernel_launch(void* const* d_in, const int* in_sizes, int n_in,
                              void* d_out, int out_size)
{
    const float* x  = (const float*)d_in[0];
    const float* Wq = (const float*)d_in[1];
    const float* bq = (const float*)d_in[2];
    const float* Wk = (const float*)d_in[3];
    const float* bk = (const float*)d_in[4];
    const float* Wv = (const float*)d_in[5];
    const float* bv = (const float*)d_in[6];
    float* out = (float*)d_out;

    split_x_kernel<<<M_TOT * K_TOT / 2048, 256>>>(x);
    split_w_kernel<<<dim3(32, 32, 3), dim3(32, 32)>>>(Wq, Wk, Wv);

    cudaFuncSetAttribute(qkv_gemm_mma, cudaFuncAttributeMaxDynamicSharedMemorySize, SMEM_DYN);
    qkv_gemm_mma<<<dim3(8, 64, 3), 512, SMEM_DYN>>>(bq, bk, bv);

    attn_mma<<<M_TOT / 8, 256>>>(out);
}

// round 7
// speedup vs baseline: 6.4088x; 1.0208x over previous
#include <cuda_runtime.h>
#include <cuda_fp16.h>
#include <cstdint>

// Problem shape: B=4, S=4096, E=1024, H=16, D=64
#define M_TOT 16384
#define N_TOT 1024
#define K_TOT 1024

// ---------------- static device scratch ----------------
__device__ __half g_qkvh[3][(size_t)M_TOT * N_TOT];        // 96 MB (fp16 q,k,v)
__device__ __half g_xh[(size_t)M_TOT * K_TOT];             // 32 MB  (fp16(x))
__device__ __half g_wh[3][(size_t)K_TOT * N_TOT];          // transposed [n][k], fp16(W)

// ---------------- PTX helpers (sm_80-compatible) ----------------
__device__ __forceinline__ uint32_t sptr(const void* p) {
    return (uint32_t)__cvta_generic_to_shared(p);
}
__device__ __forceinline__ void cpa16(uint32_t s, const void* g) {
    asm volatile("cp.async.cg.shared.global [%0], [%1], 16;" :: "r"(s), "l"(g) : "memory");
}
__device__ __forceinline__ void cp_commit() { asm volatile("cp.async.commit_group;" ::: "memory"); }
template <int N> __device__ __forceinline__ void cp_wait() {
    asm volatile("cp.async.wait_group %0;" :: "n"(N) : "memory");
}
__device__ __forceinline__ void ldm_x4(uint32_t& r0, uint32_t& r1, uint32_t& r2, uint32_t& r3,
                                       uint32_t addr) {
    asm volatile("ldmatrix.sync.aligned.m8n8.x4.shared.b16 {%0,%1,%2,%3}, [%4];"
                 : "=r"(r0), "=r"(r1), "=r"(r2), "=r"(r3) : "r"(addr));
}
__device__ __forceinline__ void ldm_x4t(uint32_t& r0, uint32_t& r1, uint32_t& r2, uint32_t& r3,
                                        uint32_t addr) {
    asm volatile("ldmatrix.sync.aligned.m8n8.x4.trans.shared.b16 {%0,%1,%2,%3}, [%4];"
                 : "=r"(r0), "=r"(r1), "=r"(r2), "=r"(r3) : "r"(addr));
}
__device__ __forceinline__ void mma_f16(float* c, const uint32_t* a, const uint32_t* b) {
    asm volatile(
        "mma.sync.aligned.m16n8k16.row.col.f32.f16.f16.f32 "
        "{%0,%1,%2,%3}, {%4,%5,%6,%7}, {%8,%9}, {%0,%1,%2,%3};"
        : "+f"(c[0]), "+f"(c[1]), "+f"(c[2]), "+f"(c[3])
        : "r"(a[0]), "r"(a[1]), "r"(a[2]), "r"(a[3]), "r"(b[0]), "r"(b[1]));
}

#define SWZ(o) ((o) ^ (((o) >> 3) & 0x70))

// ---------------- combined convert kernel ----------------
// blocks [0, 8192): x -> fp16   |   blocks [8192, 8192+3072): W transpose+convert
__global__ __launch_bounds__(256)
void convert_kernel(const float* __restrict__ x,
                    const float* __restrict__ Wq, const float* __restrict__ Wk,
                    const float* __restrict__ Wv)
{
    const int b = blockIdx.x;
    const int tid = threadIdx.x;
    if (b < 8192) {
        size_t i = ((size_t)b * 256 + tid) * 8;
        float4 v0 = *(const float4*)(x + i);
        float4 v1 = *(const float4*)(x + i + 4);
        union { __half h[8]; uint4 u; } p;
        p.h[0] = __float2half_rn(v0.x); p.h[1] = __float2half_rn(v0.y);
        p.h[2] = __float2half_rn(v0.z); p.h[3] = __float2half_rn(v0.w);
        p.h[4] = __float2half_rn(v1.x); p.h[5] = __float2half_rn(v1.y);
        p.h[6] = __float2half_rn(v1.z); p.h[7] = __float2half_rn(v1.w);
        *(uint4*)(g_xh + i) = p.u;
    } else {
        const int wb = b - 8192;               // 0..3071
        const int z = wb >> 10;                // 0..2
        const int t = wb & 1023;               // 32x32 tiles: 32 x 32 grid
        const int k0 = (t >> 5) * 32, n0 = (t & 31) * 32;
        const float* __restrict__ W = (z == 0) ? Wq : (z == 1) ? Wk : Wv;
        __shared__ float tile[32][33];
        const int tx = tid & 31, ty0 = tid >> 5;   // 8 rows per pass
        #pragma unroll
        for (int r = 0; r < 4; r++) {
            int y = ty0 + r * 8;
            tile[y][tx] = W[(size_t)(k0 + y) * N_TOT + n0 + tx];
        }
        __syncthreads();
        #pragma unroll
        for (int r = 0; r < 4; r++) {
            int y = ty0 + r * 8;
            g_wh[z][(size_t)(n0 + y) * K_TOT + k0 + tx] = __float2half_rn(tile[tx][y]);
        }
    }
}

// ---------------- persistent fp16 GEMM: qkv = xh@wh + bias (fp16 out) ----------------
// 148 persistent CTAs, 512 threads, tile 256x128, BK=64, 4-slot continuous pipeline.
static constexpr int STAGE_BYTES = 49152;
static constexpr uint32_t OFF_B = 32768;
static constexpr int NSTAGE = 4;
static constexpr int SMEM_DYN = NSTAGE * STAGE_BYTES;   // 192 KB
static constexpr int GEMM_GRID = 148;
static constexpr int NTILES = 3 * 64 * 8;               // 1536
static constexpr int KT_PER_TILE = 16;                  // 1024 / 64

__device__ __forceinline__ void tile_coord(int t, int& z, int& m0, int& n0) {
    z = t / 512;
    int r = t - z * 512;
    m0 = (r >> 3) * 256;
    n0 = (r & 7) * 128;
}

__device__ __forceinline__ void load_stage(uint32_t sb, int kt, int m0, int n0, int tid,
                                           const __half* __restrict__ wh)
{
    const int kb = kt * 64;
    #pragma unroll
    for (int i = 0; i < 4; i++) {                 // A: 256 rows x 8 chunks of 16B
        int idx = tid + i * 512;
        int row = idx >> 3, c = idx & 7;
        uint32_t so = SWZ((uint32_t)(row * 128 + c * 16));
        cpa16(sb + so, g_xh + (((size_t)(m0 + row)) << 10) + kb + c * 8);
    }
    #pragma unroll
    for (int i = 0; i < 2; i++) {                 // B: 128 rows x 8 chunks
        int idx = tid + i * 512;
        int row = idx >> 3, c = idx & 7;
        uint32_t so = SWZ((uint32_t)(row * 128 + c * 16));
        cpa16(sb + OFF_B + so, wh + (((size_t)(n0 + row)) << 10) + kb + c * 8);
    }
}

__global__ __launch_bounds__(512, 1)
void qkv_gemm_mma(const float* __restrict__ bq, const float* __restrict__ bk,
                  const float* __restrict__ bv)
{
    extern __shared__ __align__(16) char dsm[];

    const int tid = threadIdx.x;
    const int lane = tid & 31;
    const int wid = tid >> 5;
    const int warp_m = wid >> 2;       // 0..3
    const int warp_n = wid & 3;        // 0..3
    const int cta = blockIdx.x;

    const int my_ntiles = (NTILES - cta + GEMM_GRID - 1) / GEMM_GRID;
    const int total = my_ntiles * KT_PER_TILE;

    const uint32_t sbase = sptr(dsm);

    float acc[4][4][4];
    #pragma unroll
    for (int mi = 0; mi < 4; mi++)
        #pragma unroll
        for (int ni = 0; ni < 4; ni++)
            #pragma unroll
            for (int r = 0; r < 4; r++) acc[mi][ni][r] = 0.f;

    const int a_row = warp_m * 64 + ((lane >> 3) & 1) * 8 + (lane & 7);
    const int a_cb0 = (lane >> 4) * 16;
    const int b_row = warp_n * 32 + ((lane >> 4) & 1) * 8 + (lane & 7);
    const int b_cb0 = ((lane >> 3) & 1) * 16;

    // prologue: global stages 0..2
    #pragma unroll
    for (int g = 0; g < 3; g++) {
        if (g < total) {
            int t = cta + (g >> 4) * GEMM_GRID;
            int z, m0, n0;
            tile_coord(t, z, m0, n0);
            load_stage(sbase + (uint32_t)(g & 3) * STAGE_BYTES, g & 15, m0, n0, tid, g_wh[z]);
        }
        cp_commit();
    }

    for (int g = 0; g < total; ++g) {
        cp_wait<2>();
        __syncthreads();
        const int gp = g + 3;
        if (gp < total) {
            int t = cta + (gp >> 4) * GEMM_GRID;
            int z, m0, n0;
            tile_coord(t, z, m0, n0);
            load_stage(sbase + (uint32_t)(gp & 3) * STAGE_BYTES, gp & 15, m0, n0, tid, g_wh[z]);
        }
        cp_commit();

        const uint32_t abase = sbase + (uint32_t)(g & 3) * STAGE_BYTES;

        #pragma unroll
        for (int ks = 0; ks < 4; ks++) {
            uint32_t a[4][4], b[4][2];
            #pragma unroll
            for (int mi = 0; mi < 4; mi++) {
                uint32_t off = (uint32_t)((a_row + mi * 16) * 128 + ks * 32 + a_cb0);
                ldm_x4(a[mi][0], a[mi][1], a[mi][2], a[mi][3], abase + SWZ(off));
            }
            #pragma unroll
            for (int pr = 0; pr < 2; pr++) {
                uint32_t off = (uint32_t)((b_row + pr * 16) * 128 + ks * 32 + b_cb0);
                uint32_t r0, r1, r2, r3;
                ldm_x4(r0, r1, r2, r3, abase + OFF_B + SWZ(off));
                b[pr * 2 + 0][0] = r0; b[pr * 2 + 0][1] = r1;
                b[pr * 2 + 1][0] = r2; b[pr * 2 + 1][1] = r3;
            }
            #pragma unroll
            for (int mi = 0; mi < 4; mi++)
                #pragma unroll
                for (int ni = 0; ni < 4; ni++)
                    mma_f16(acc[mi][ni], a[mi], b[ni]);
        }

        if ((g & 15) == 15) {
            // tile epilogue (register-only; next tile's loads already in flight)
            int t = cta + (g >> 4) * GEMM_GRID;
            int z, m0, n0;
            tile_coord(t, z, m0, n0);
            const float* __restrict__ bias = (z == 0) ? bq : (z == 1) ? bk : bv;
            __half* __restrict__ out = g_qkvh[z];
            const int row_base = m0 + warp_m * 64 + (lane >> 2);
            const int col_loc = warp_n * 32 + (lane & 3) * 2;
            #pragma unroll
            for (int mi = 0; mi < 4; mi++) {
                #pragma unroll
                for (int ni = 0; ni < 4; ni++) {
                    const int col = col_loc + ni * 8;
                    const float b0 = __ldg(bias + n0 + col);
                    const float b1 = __ldg(bias + n0 + col + 1);
                    __half* p0 = out + (size_t)(row_base + mi * 16) * N_TOT + n0 + col;
                    __half* p1 = p0 + 8 * N_TOT;
                    *(__half2*)p0 = __floats2half2_rn(acc[mi][ni][0] + b0, acc[mi][ni][1] + b1);
                    *(__half2*)p1 = __floats2half2_rn(acc[mi][ni][2] + b0, acc[mi][ni][3] + b1);
                    #pragma unroll
                    for (int r = 0; r < 4; r++) acc[mi][ni][r] = 0.f;
                }
            }
        }
    }
}

// ---------------- tensor-core per-token attention ----------------
__global__ __launch_bounds__(256)
void attn_mma(float* __restrict__ out)
{
    __shared__ __align__(128) char sm[8 * 6144];   // 48 KB: 8 tokens x (q|k|v)

    const int lane = threadIdx.x & 31;
    const int wid = threadIdx.x >> 5;
    const int token = blockIdx.x * 8 + wid;
    const uint32_t tb = sptr(sm) + (uint32_t)wid * 6144;

    #pragma unroll
    for (int j = 0; j < 12; j++) {
        int idx = lane + j * 32;
        int mat = idx >> 7;
        int rem = idx & 127;
        int r = rem >> 3, c = rem & 7;
        cpa16(tb + (uint32_t)mat * 2048 + SWZ((uint32_t)(r * 128 + c * 16)),
              g_qkvh[mat] + ((size_t)token << 10) + r * 64 + c * 8);
    }
    cp_commit();
    cp_wait<0>();
    __syncwarp();

    const int a_row = ((lane >> 3) & 1) * 8 + (lane & 7);
    const int a_cb = (lane >> 4) * 16;
    const int b_row = ((lane >> 4) & 1) * 8 + (lane & 7);
    const int b_cb = ((lane >> 3) & 1) * 16;
    const int v_row = ((lane >> 3) & 1) * 8 + (lane & 7);
    const int v_cb = (lane >> 4) * 16;

    float attc[2][4] = {{0.f, 0.f, 0.f, 0.f}, {0.f, 0.f, 0.f, 0.f}};
    #pragma unroll
    for (int kc = 0; kc < 4; kc++) {
        uint32_t a[4];
        ldm_x4(a[0], a[1], a[2], a[3], tb + SWZ((uint32_t)(a_row * 128 + kc * 32 + a_cb)));
        uint32_t r0, r1, r2, r3;
        ldm_x4(r0, r1, r2, r3, tb + 2048 + SWZ((uint32_t)(b_row * 128 + kc * 32 + b_cb)));
        uint32_t blo[2] = {r0, r1}, bhi[2] = {r2, r3};
        mma_f16(attc[0], a, blo);
        mma_f16(attc[1], a, bhi);
    }

    uint32_t aa[4];
    {
        __half2 h0 = __floats2half2_rn(attc[0][0], attc[0][1]);
        __half2 h1 = __floats2half2_rn(attc[0][2], attc[0][3]);
        __half2 h2 = __floats2half2_rn(attc[1][0], attc[1][1]);
        __half2 h3 = __floats2half2_rn(attc[1][2], attc[1][3]);
        aa[0] = *(uint32_t*)&h0;
        aa[1] = *(uint32_t*)&h1;
        aa[2] = *(uint32_t*)&h2;
        aa[3] = *(uint32_t*)&h3;
    }

    float* __restrict__ op = out + ((size_t)token << 10);
    const int row = lane >> 2;
    const int cl = (lane & 3) * 2;
    #pragma unroll
    for (int dc = 0; dc < 4; dc++) {
        uint32_t r0, r1, r2, r3;
        ldm_x4t(r0, r1, r2, r3, tb + 4096 + SWZ((uint32_t)(v_row * 128 + dc * 32 + v_cb)));
        uint32_t blo[2] = {r0, r1}, bhi[2] = {r2, r3};
        float oc0[4] = {0.f, 0.f, 0.f, 0.f};
        float oc1[4] = {0.f, 0.f, 0.f, 0.f};
        mma_f16(oc0, aa, blo);
        mma_f16(oc1, aa, bhi);
        float* p = op + row * 64 + dc * 16 + cl;
        *(float2*)(p) = make_float2(oc0[0], oc0[1]);
        *(float2*)(p + 8 * 64) = make_float2(oc0[2], oc0[3]);
        *(float2*)(p + 8) = make_float2(oc1[0], oc1[1]);
        *(float2*)(p + 8 * 64 + 8) = make_float2(oc1[2], oc1[3]);
    }
}

extern "C" void kernel_launch(void* const* d_in, const int* in_sizes, int n_in,
                              void* d_out, int out_size)
{
    const float* x  = (const float*)d_in[0];
    const float* Wq = (const float*)d_in[1];
    const float* bq = (const float*)d_in[2];
    const float* Wk = (const float*)d_in[3];
    const float* bk = (const float*)d_in[4];
    const float* Wv = (const float*)d_in[5];
    const float* bv = (const float*)d_in[6];
    float* out = (float*)d_out;

    convert_kernel<<<8192 + 3072, 256>>>(x, Wq, Wk, Wv);

    cudaFuncSetAttribute(qkv_gemm_mma, cudaFuncAttributeMaxDynamicSharedMemorySize, SMEM_DYN);
    qkv_gemm_mma<<<GEMM_GRID, 512, SMEM_DYN>>>(bq, bk, bv);

    attn_mma<<<M_TOT / 8, 256>>>(out);
}